// round 5
// baseline (speedup 1.0000x reference)
#include <cuda_runtime.h>
#include <cuda_fp16.h>
#include <math.h>
#include <cstdint>

#define BATCH 2
#define SEQ   2048
#define HID   2048
#define NHEAD 16
#define HDIM  128
#define FFD   8192
#define ROWS  (BATCH*SEQ)   // 4096

// ---------------- scratch ---------------------------------------------------
__device__ float g_q [ROWS*HID];
__device__ float g_k [ROWS*HID];
__device__ float g_v [ROWS*HID];
__device__ float g_h [ROWS*HID];
__device__ __half g_xnh[ROWS*HID];
__device__ __half g_xnl[ROWS*HID];
__device__ __half g_atth[ROWS*HID];
__device__ __half g_attl[ROWS*HID];
__device__ __half g_hnh[ROWS*HID];
__device__ __half g_hnl[ROWS*HID];
__device__ __half g_ffh[(size_t)ROWS*FFD];
__device__ __half g_ffl[(size_t)ROWS*FFD];
__device__ __half g_wqh[HID*HID];   __device__ __half g_wql[HID*HID];
__device__ __half g_wkh[HID*HID];   __device__ __half g_wkl[HID*HID];
__device__ __half g_wvh[HID*HID];   __device__ __half g_wvl[HID*HID];
__device__ __half g_woh[HID*HID];   __device__ __half g_wol[HID*HID];
__device__ __half g_winh[(size_t)HID*FFD];  __device__ __half g_winl[(size_t)HID*FFD];
__device__ __half g_wouth[(size_t)HID*FFD]; __device__ __half g_woutl[(size_t)HID*FFD];

// ============================ helpers ========================================
__device__ __forceinline__ uint32_t smem_u32(const void* p) {
    uint32_t a;
    asm("{ .reg .u64 t; cvta.to.shared.u64 t, %1; cvt.u32.u64 %0, t; }"
        : "=r"(a) : "l"(p));
    return a;
}
__device__ __forceinline__ void cp16(uint32_t dst, const void* src) {
    asm volatile("cp.async.cg.shared.global [%0], [%1], 16;" :: "r"(dst), "l"(src));
}
__device__ __forceinline__ void cp_commit() { asm volatile("cp.async.commit_group;"); }
template<int N> __device__ __forceinline__ void cp_wait() {
    asm volatile("cp.async.wait_group %0;" :: "n"(N));
}
__device__ __forceinline__ void ldsm_x4(uint32_t* r, uint32_t addr) {
    asm volatile("ldmatrix.sync.aligned.m8n8.x4.shared.b16 {%0,%1,%2,%3}, [%4];"
        : "=r"(r[0]), "=r"(r[1]), "=r"(r[2]), "=r"(r[3]) : "r"(addr));
}
__device__ __forceinline__ void ldsm_x4_t(uint32_t* r, uint32_t addr) {
    asm volatile("ldmatrix.sync.aligned.m8n8.x4.trans.shared.b16 {%0,%1,%2,%3}, [%4];"
        : "=r"(r[0]), "=r"(r[1]), "=r"(r[2]), "=r"(r[3]) : "r"(addr));
}
__device__ __forceinline__ void mma_f16(float* c, const uint32_t* a, const uint32_t* b) {
    asm volatile("mma.sync.aligned.m16n8k16.row.col.f32.f16.f16.f32 "
        "{%0,%1,%2,%3}, {%4,%5,%6,%7}, {%8,%9}, {%0,%1,%2,%3};"
        : "+f"(c[0]), "+f"(c[1]), "+f"(c[2]), "+f"(c[3])
        : "r"(a[0]), "r"(a[1]), "r"(a[2]), "r"(a[3]), "r"(b[0]), "r"(b[1]));
}
__device__ __forceinline__ float gelu_tanh(float x) {
    float x3 = x * x * x;
    float t  = tanhf(0.7978845608028654f * (x + 0.044715f * x3));
    return 0.5f * x * (1.0f + t);
}
__device__ __forceinline__ void split_val(float v, __half& hi, __half& lo) {
    hi = __float2half_rn(v);
    lo = __float2half_rn(v - __half2float(hi));
}

// ============================================================================
// split-fp16 tensor-core GEMM (3-term): C = Ahi*Bhi + Ahi*Blo + Alo*Bhi
// ============================================================================
#define BM 128
#define BN 128
#define BKH 32
#define LDAH 40
#define LDBH 136
#define ASZH (BM*LDAH)
#define BSZH (BKH*LDBH)
#define STG 5
#define STAGEH (2*ASZH + 2*BSZH)       // 18944 halves per stage
#define GEMM_SMEM (STG*STAGEH*2)       // 189440 bytes

template<int ACT>
__global__ __launch_bounds__(256) void tc_gemm(
    const __half* __restrict__ Ahi, const __half* __restrict__ Alo,
    const __half* __restrict__ Bhi, const __half* __restrict__ Blo,
    const float* __restrict__ Res, float* __restrict__ Cf,
    __half* __restrict__ Chi, __half* __restrict__ Clo,
    int N_, int K)
{
    extern __shared__ __align__(16) __half smem[];

    const int tid  = threadIdx.x;
    const int wid  = tid >> 5;
    const int lane = tid & 31;
    const int gid  = lane >> 2;
    const int tg   = lane & 3;
    const int wm   = wid & 3;
    const int wn   = wid >> 2;
    const int bm = blockIdx.y * BM;
    const int bn = blockIdx.x * BN;
    const int nK = K / BKH;

    const int a_m = lane & 15;
    const int a_k = (lane >> 4) * 8;
    const int b_k = ((lane >> 3) & 1) * 8 + (lane & 7);
    const int b_n = (lane >> 4) * 8;

    auto load_stage = [&](int s, int kt) {
        const int k0 = kt * BKH;
        __half* Ah = smem + s*STAGEH;
        __half* Al = Ah + ASZH;
        __half* Bh = Al + ASZH;
        __half* Bl = Bh + BSZH;
        #pragma unroll
        for (int i = 0; i < 2; i++) {
            const int c  = tid + 256*i;
            const int ar = c >> 2, ak = (c & 3) << 3;
            cp16(smem_u32(&Ah[ar*LDAH + ak]), &Ahi[(size_t)(bm + ar)*K + k0 + ak]);
            cp16(smem_u32(&Al[ar*LDAH + ak]), &Alo[(size_t)(bm + ar)*K + k0 + ak]);
            const int bk = c >> 4, bnn = (c & 15) << 3;
            cp16(smem_u32(&Bh[bk*LDBH + bnn]), &Bhi[(size_t)(k0 + bk)*N_ + bn + bnn]);
            cp16(smem_u32(&Bl[bk*LDBH + bnn]), &Blo[(size_t)(k0 + bk)*N_ + bn + bnn]);
        }
        cp_commit();
    };

    float acc[2][8][4];
    #pragma unroll
    for (int mt = 0; mt < 2; mt++)
        #pragma unroll
        for (int nt = 0; nt < 8; nt++)
            #pragma unroll
            for (int r = 0; r < 4; r++) acc[mt][nt][r] = 0.0f;

    #pragma unroll
    for (int s = 0; s < STG-1; s++) load_stage(s, s);

    for (int kt = 0; kt < nK; kt++) {
        cp_wait<STG-2>();
        __syncthreads();
        const int s = kt % STG;
        const __half* Ah = smem + s*STAGEH;
        const __half* Al = Ah + ASZH;
        const __half* Bh = Al + ASZH;
        const __half* Bl = Bh + BSZH;

        #pragma unroll
        for (int kk = 0; kk < 2; kk++) {
            uint32_t ah[2][4], al[2][4];
            #pragma unroll
            for (int mt = 0; mt < 2; mt++) {
                const int mrow = wm*32 + mt*16 + a_m;
                const int koff = kk*16 + a_k;
                ldsm_x4(ah[mt], smem_u32(&Ah[mrow*LDAH + koff]));
                ldsm_x4(al[mt], smem_u32(&Al[mrow*LDAH + koff]));
            }
            uint32_t bh[4][4], bl[4][4];
            #pragma unroll
            for (int ng = 0; ng < 4; ng++) {
                const int koff = kk*16 + b_k;
                const int noff = wn*64 + ng*16 + b_n;
                ldsm_x4_t(bh[ng], smem_u32(&Bh[koff*LDBH + noff]));
                ldsm_x4_t(bl[ng], smem_u32(&Bl[koff*LDBH + noff]));
            }
            #pragma unroll
            for (int mt = 0; mt < 2; mt++)
                #pragma unroll
                for (int nt = 0; nt < 8; nt++) {
                    const uint32_t* bhp = &bh[nt >> 1][(nt & 1) * 2];
                    const uint32_t* blp = &bl[nt >> 1][(nt & 1) * 2];
                    mma_f16(acc[mt][nt], ah[mt], bhp);
                    mma_f16(acc[mt][nt], ah[mt], blp);
                    mma_f16(acc[mt][nt], al[mt], bhp);
                }
        }
        if (kt + STG - 1 < nK)
            load_stage((kt + STG - 1) % STG, kt + STG - 1);
    }

    // ---- epilogue ----
    #pragma unroll
    for (int mt = 0; mt < 2; mt++) {
        #pragma unroll
        for (int half_ = 0; half_ < 2; half_++) {
            const int r = bm + wm*32 + mt*16 + gid + half_*8;
            #pragma unroll
            for (int nt = 0; nt < 8; nt++) {
                const int cc = bn + wn*64 + nt*8 + tg*2;
                float v0 = acc[mt][nt][half_*2 + 0];
                float v1 = acc[mt][nt][half_*2 + 1];
                if (ACT == 2) {
                    v0 = gelu_tanh(v0); v1 = gelu_tanh(v1);
                    __half h0, l0, h1, l1;
                    split_val(v0, h0, l0); split_val(v1, h1, l1);
                    *reinterpret_cast<__half2*>(&Chi[(size_t)r*N_ + cc]) = __halves2half2(h0, h1);
                    *reinterpret_cast<__half2*>(&Clo[(size_t)r*N_ + cc]) = __halves2half2(l0, l1);
                } else {
                    if (ACT == 1) {
                        const float2 rr = *reinterpret_cast<const float2*>(&Res[(size_t)r*N_ + cc]);
                        v0 += rr.x; v1 += rr.y;
                    }
                    float2 o; o.x = v0; o.y = v1;
                    *reinterpret_cast<float2*>(&Cf[(size_t)r*N_ + cc]) = o;
                }
            }
        }
    }
}

// ------------- weight split: 4 square weights in one launch (z-indexed) -----
__global__ void split4_kernel(const float* __restrict__ w0, __half* h0, __half* l0,
                              const float* __restrict__ w1, __half* h1, __half* l1,
                              const float* __restrict__ w2, __half* h2, __half* l2,
                              const float* __restrict__ w3, __half* h3, __half* l3,
                              int n4)
{
    const float* in; __half* hi; __half* lo;
    switch (blockIdx.y) {
        case 0: in = w0; hi = h0; lo = l0; break;
        case 1: in = w1; hi = h1; lo = l1; break;
        case 2: in = w2; hi = h2; lo = l2; break;
        default: in = w3; hi = h3; lo = l3; break;
    }
    const int i = blockIdx.x*blockDim.x + threadIdx.x;
    if (i >= n4) return;
    float4 v = reinterpret_cast<const float4*>(in)[i];
    __half a0,b0,a1,b1,a2,b2,a3,b3;
    split_val(v.x, a0, b0); split_val(v.y, a1, b1);
    split_val(v.z, a2, b2); split_val(v.w, a3, b3);
    reinterpret_cast<__half2*>(hi)[2*i+0] = __halves2half2(a0, a1);
    reinterpret_cast<__half2*>(hi)[2*i+1] = __halves2half2(a2, a3);
    reinterpret_cast<__half2*>(lo)[2*i+0] = __halves2half2(b0, b1);
    reinterpret_cast<__half2*>(lo)[2*i+1] = __halves2half2(b2, b3);
}
__global__ void split2_kernel(const float* __restrict__ w0, __half* h0, __half* l0,
                              const float* __restrict__ w1, __half* h1, __half* l1,
                              int n4)
{
    const float* in = blockIdx.y ? w1 : w0;
    __half* hi = blockIdx.y ? h1 : h0;
    __half* lo = blockIdx.y ? l1 : l0;
    const int i = blockIdx.x*blockDim.x + threadIdx.x;
    if (i >= n4) return;
    float4 v = reinterpret_cast<const float4*>(in)[i];
    __half a0,b0,a1,b1,a2,b2,a3,b3;
    split_val(v.x, a0, b0); split_val(v.y, a1, b1);
    split_val(v.z, a2, b2); split_val(v.w, a3, b3);
    reinterpret_cast<__half2*>(hi)[2*i+0] = __halves2half2(a0, a1);
    reinterpret_cast<__half2*>(hi)[2*i+1] = __halves2half2(a2, a3);
    reinterpret_cast<__half2*>(lo)[2*i+0] = __halves2half2(b0, b1);
    reinterpret_cast<__half2*>(lo)[2*i+1] = __halves2half2(b2, b3);
}

// ---------------- LayerNorm -> split fp16 outputs ---------------------------
__global__ void ln_kernel(const float* __restrict__ x,
                          const float* __restrict__ g,
                          const float* __restrict__ b,
                          __half* __restrict__ ohi, __half* __restrict__ olo)
{
    const int row = blockIdx.x;
    const int tid = threadIdx.x;
    const float* xr = x + (size_t)row * HID;

    float4 v0 = reinterpret_cast<const float4*>(xr)[tid];
    float4 v1 = reinterpret_cast<const float4*>(xr)[tid + 256];

    __shared__ float red[8];

    float s = v0.x+v0.y+v0.z+v0.w + v1.x+v1.y+v1.z+v1.w;
    #pragma unroll
    for (int o = 16; o > 0; o >>= 1) s += __shfl_xor_sync(0xffffffffu, s, o);
    if ((tid & 31) == 0) red[tid >> 5] = s;
    __syncthreads();
    float mu = (red[0]+red[1]+red[2]+red[3]+red[4]+red[5]+red[6]+red[7]) * (1.0f/HID);
    __syncthreads();

    float d0x=v0.x-mu, d0y=v0.y-mu, d0z=v0.z-mu, d0w=v0.w-mu;
    float d1x=v1.x-mu, d1y=v1.y-mu, d1z=v1.z-mu, d1w=v1.w-mu;
    float sq = d0x*d0x+d0y*d0y+d0z*d0z+d0w*d0w + d1x*d1x+d1y*d1y+d1z*d1z+d1w*d1w;
    #pragma unroll
    for (int o = 16; o > 0; o >>= 1) sq += __shfl_xor_sync(0xffffffffu, sq, o);
    if ((tid & 31) == 0) red[tid >> 5] = sq;
    __syncthreads();
    float var = (red[0]+red[1]+red[2]+red[3]+red[4]+red[5]+red[6]+red[7]) * (1.0f/HID);
    float rstd = rsqrtf(var + 1e-5f);

    float4 g0 = reinterpret_cast<const float4*>(g)[tid];
    float4 g1 = reinterpret_cast<const float4*>(g)[tid + 256];
    float4 b0 = reinterpret_cast<const float4*>(b)[tid];
    float4 b1 = reinterpret_cast<const float4*>(b)[tid + 256];

    float o0[4] = { d0x*rstd*g0.x + b0.x, d0y*rstd*g0.y + b0.y,
                    d0z*rstd*g0.z + b0.z, d0w*rstd*g0.w + b0.w };
    float o1[4] = { d1x*rstd*g1.x + b1.x, d1y*rstd*g1.y + b1.y,
                    d1z*rstd*g1.z + b1.z, d1w*rstd*g1.w + b1.w };

    const size_t base = (size_t)row * HID;
    __half h[4], l[4];
    #pragma unroll
    for (int j = 0; j < 4; j++) split_val(o0[j], h[j], l[j]);
    reinterpret_cast<__half2*>(ohi + base)[tid*2+0] = __halves2half2(h[0], h[1]);
    reinterpret_cast<__half2*>(ohi + base)[tid*2+1] = __halves2half2(h[2], h[3]);
    reinterpret_cast<__half2*>(olo + base)[tid*2+0] = __halves2half2(l[0], l[1]);
    reinterpret_cast<__half2*>(olo + base)[tid*2+1] = __halves2half2(l[2], l[3]);
    #pragma unroll
    for (int j = 0; j < 4; j++) split_val(o1[j], h[j], l[j]);
    reinterpret_cast<__half2*>(ohi + base)[(tid+256)*2+0] = __halves2half2(h[0], h[1]);
    reinterpret_cast<__half2*>(ohi + base)[(tid+256)*2+1] = __halves2half2(h[2], h[3]);
    reinterpret_cast<__half2*>(olo + base)[(tid+256)*2+0] = __halves2half2(l[0], l[1]);
    reinterpret_cast<__half2*>(olo + base)[(tid+256)*2+1] = __halves2half2(l[2], l[3]);
}

// ---------------- Flash attention (causal, fp32, vectorized LDS) ------------
// Thread (tx,ty): scores cols tx*4+jj, output cols tx*8+c (contiguous -> LDS.128)
#define QSTRIDE 132
#define KSTRIDE 68
#define PSTRIDE 68

__global__ __launch_bounds__(256) void flash_kernel(
    const float* __restrict__ Q, const float* __restrict__ K,
    const float* __restrict__ V,
    __half* __restrict__ Ohi, __half* __restrict__ Olo)
{
    extern __shared__ float sm[];
    float* Qs = sm;
    float* Kt = Qs + 64*QSTRIDE;
    float* Vs = Kt + 128*KSTRIDE;
    float* Ps = Vs + 64*QSTRIDE;

    const int tid = threadIdx.x;
    const int tx = tid & 15;
    const int ty = tid >> 4;
    const int bh = blockIdx.y;
    const int b  = bh >> 4;
    const int h  = bh & 15;
    const int qb = blockIdx.x;
    const size_t rowbase = (size_t)b * SEQ;
    const int colbase = h * HDIM;
    const float scale = 0.088388347648318447f;

    #pragma unroll
    for (int it = 0; it < 8; ++it) {
        int idx = it * 256 + tid;
        int r  = idx >> 5;
        int c4 = (idx & 31) << 2;
        float4 qv = *reinterpret_cast<const float4*>(
            &Q[(rowbase + qb*64 + r) * HID + colbase + c4]);
        *reinterpret_cast<float4*>(&Qs[r*QSTRIDE + c4]) = qv;
    }

    float m[4], l[4], o[4][8];
    #pragma unroll
    for (int i = 0; i < 4; i++) {
        m[i] = -1e30f; l[i] = 0.0f;
        #pragma unroll
        for (int c = 0; c < 8; c++) o[i][c] = 0.0f;
    }

    for (int kb = 0; kb <= qb; ++kb) {
        __syncthreads();
        #pragma unroll
        for (int it = 0; it < 8; ++it) {
            int idx = it * 256 + tid;
            int r  = idx >> 5;
            int c4 = (idx & 31) << 2;
            const size_t grow = (rowbase + kb*64 + r) * (size_t)HID + colbase + c4;
            float4 kv = *reinterpret_cast<const float4*>(&K[grow]);
            Kt[(c4+0)*KSTRIDE + r] = kv.x;
            Kt[(c4+1)*KSTRIDE + r] = kv.y;
            Kt[(c4+2)*KSTRIDE + r] = kv.z;
            Kt[(c4+3)*KSTRIDE + r] = kv.w;
            float4 vv = *reinterpret_cast<const float4*>(&V[grow]);
            *reinterpret_cast<float4*>(&Vs[r*QSTRIDE + c4]) = vv;
        }
        __syncthreads();

        // scores: rows ty*4+i, cols tx*4+jj (contiguous per thread)
        float s[4][4];
        #pragma unroll
        for (int i = 0; i < 4; i++)
            #pragma unroll
            for (int jj = 0; jj < 4; jj++) s[i][jj] = 0.0f;

        #pragma unroll 4
        for (int d = 0; d < HDIM; ++d) {
            const float4 kr = *reinterpret_cast<const float4*>(&Kt[d*KSTRIDE + tx*4]);
            #pragma unroll
            for (int i = 0; i < 4; i++) {
                const float qv = Qs[(ty*4 + i)*QSTRIDE + d];
                s[i][0] = fmaf(qv, kr.x, s[i][0]);
                s[i][1] = fmaf(qv, kr.y, s[i][1]);
                s[i][2] = fmaf(qv, kr.z, s[i][2]);
                s[i][3] = fmaf(qv, kr.w, s[i][3]);
            }
        }

        const bool diag = (kb == qb);
        #pragma unroll
        for (int i = 0; i < 4; i++) {
            const int qg = qb*64 + ty*4 + i;
            float mx = -1e30f;
            #pragma unroll
            for (int jj = 0; jj < 4; jj++) {
                float v = s[i][jj] * scale;
                if (diag && (kb*64 + tx*4 + jj) > qg) v = -1e30f;
                s[i][jj] = v;
                mx = fmaxf(mx, v);
            }
            #pragma unroll
            for (int off = 8; off > 0; off >>= 1)
                mx = fmaxf(mx, __shfl_xor_sync(0xffffffffu, mx, off));
            float mnew = fmaxf(m[i], mx);
            float corr = __expf(m[i] - mnew);
            float rs = 0.0f;
            #pragma unroll
            for (int jj = 0; jj < 4; jj++) {
                float p = __expf(s[i][jj] - mnew);
                s[i][jj] = p;
                rs += p;
            }
            #pragma unroll
            for (int off = 8; off > 0; off >>= 1)
                rs += __shfl_xor_sync(0xffffffffu, rs, off);
            l[i] = l[i]*corr + rs;
            m[i] = mnew;
            #pragma unroll
            for (int c = 0; c < 8; c++) o[i][c] *= corr;
            float4 pv; pv.x = s[i][0]; pv.y = s[i][1]; pv.z = s[i][2]; pv.w = s[i][3];
            *reinterpret_cast<float4*>(&Ps[(ty*4 + i)*PSTRIDE + tx*4]) = pv;
        }
        __syncthreads();

        // PV accumulate: out cols tx*8..tx*8+7 (two float4 V loads per j)
        #pragma unroll 4
        for (int j = 0; j < 64; ++j) {
            const float4 va = *reinterpret_cast<const float4*>(&Vs[j*QSTRIDE + tx*8]);
            const float4 vb = *reinterpret_cast<const float4*>(&Vs[j*QSTRIDE + tx*8 + 4]);
            #pragma unroll
            for (int i = 0; i < 4; i++) {
                const float p = Ps[(ty*4 + i)*PSTRIDE + j];
                o[i][0] = fmaf(p, va.x, o[i][0]);
                o[i][1] = fmaf(p, va.y, o[i][1]);
                o[i][2] = fmaf(p, va.z, o[i][2]);
                o[i][3] = fmaf(p, va.w, o[i][3]);
                o[i][4] = fmaf(p, vb.x, o[i][4]);
                o[i][5] = fmaf(p, vb.y, o[i][5]);
                o[i][6] = fmaf(p, vb.z, o[i][6]);
                o[i][7] = fmaf(p, vb.w, o[i][7]);
            }
        }
    }

    #pragma unroll
    for (int i = 0; i < 4; i++) {
        const float inv = 1.0f / l[i];
        const size_t r = rowbase + qb*64 + ty*4 + i;
        __half hh[8], ll[8];
        #pragma unroll
        for (int c = 0; c < 8; c++) split_val(o[i][c] * inv, hh[c], ll[c]);
        __half2* oh = reinterpret_cast<__half2*>(&Ohi[r*HID + colbase + tx*8]);
        __half2* ol = reinterpret_cast<__half2*>(&Olo[r*HID + colbase + tx*8]);
        #pragma unroll
        for (int c = 0; c < 4; c++) {
            oh[c] = __halves2half2(hh[2*c], hh[2*c+1]);
            ol[c] = __halves2half2(ll[2*c], ll[2*c+1]);
        }
    }
}

// ============================ host side =====================================
extern "C" void kernel_launch(void* const* d_in, const int* in_sizes, int n_in,
                              void* d_out, int out_size)
{
    const float* x     = (const float*)d_in[0];
    const float* wq    = (const float*)d_in[2];
    const float* wk    = (const float*)d_in[3];
    const float* wv    = (const float*)d_in[4];
    const float* wo    = (const float*)d_in[5];
    const float* w_in  = (const float*)d_in[6];
    const float* w_out = (const float*)d_in[7];
    const float* ln1_g = (const float*)d_in[8];
    const float* ln1_b = (const float*)d_in[9];
    const float* ln2_g = (const float*)d_in[10];
    const float* ln2_b = (const float*)d_in[11];
    float* out = (float*)d_out;

    float *q, *k, *v, *h;
    __half *xnh,*xnl,*atth,*attl,*hnh,*hnl,*ffh,*ffl;
    __half *wqh,*wql,*wkh,*wkl,*wvh,*wvl,*woh,*wol,*winh,*winl,*wouth,*woutl;
    cudaGetSymbolAddress((void**)&q,  g_q);
    cudaGetSymbolAddress((void**)&k,  g_k);
    cudaGetSymbolAddress((void**)&v,  g_v);
    cudaGetSymbolAddress((void**)&h,  g_h);
    cudaGetSymbolAddress((void**)&xnh, g_xnh);   cudaGetSymbolAddress((void**)&xnl, g_xnl);
    cudaGetSymbolAddress((void**)&atth, g_atth); cudaGetSymbolAddress((void**)&attl, g_attl);
    cudaGetSymbolAddress((void**)&hnh, g_hnh);   cudaGetSymbolAddress((void**)&hnl, g_hnl);
    cudaGetSymbolAddress((void**)&ffh, g_ffh);   cudaGetSymbolAddress((void**)&ffl, g_ffl);
    cudaGetSymbolAddress((void**)&wqh, g_wqh);   cudaGetSymbolAddress((void**)&wql, g_wql);
    cudaGetSymbolAddress((void**)&wkh, g_wkh);   cudaGetSymbolAddress((void**)&wkl, g_wkl);
    cudaGetSymbolAddress((void**)&wvh, g_wvh);   cudaGetSymbolAddress((void**)&wvl, g_wvl);
    cudaGetSymbolAddress((void**)&woh, g_woh);   cudaGetSymbolAddress((void**)&wol, g_wol);
    cudaGetSymbolAddress((void**)&winh, g_winh); cudaGetSymbolAddress((void**)&winl, g_winl);
    cudaGetSymbolAddress((void**)&wouth, g_wouth); cudaGetSymbolAddress((void**)&woutl, g_woutl);

    cudaFuncSetAttribute(tc_gemm<0>, cudaFuncAttributeMaxDynamicSharedMemorySize, GEMM_SMEM);
    cudaFuncSetAttribute(tc_gemm<1>, cudaFuncAttributeMaxDynamicSharedMemorySize, GEMM_SMEM);
    cudaFuncSetAttribute(tc_gemm<2>, cudaFuncAttributeMaxDynamicSharedMemorySize, GEMM_SMEM);
    const int smem_flash = (64*QSTRIDE + 128*KSTRIDE + 64*QSTRIDE + 64*PSTRIDE) * 4;
    cudaFuncSetAttribute(flash_kernel, cudaFuncAttributeMaxDynamicSharedMemorySize, smem_flash);

    // 0. split weights (2 launches)
    {
        const int t = 256;
        dim3 g4((HID*HID/4 + t-1)/t, 4);
        split4_kernel<<<g4, t>>>(wq, wqh, wql, wk, wkh, wkl,
                                 wv, wvh, wvl, wo, woh, wol, HID*HID/4);
        dim3 g2((HID*FFD/4 + t-1)/t, 2);
        split2_kernel<<<g2, t>>>(w_in, winh, winl, w_out, wouth, woutl, HID*FFD/4);
    }

    // 1. LN1 -> split
    ln_kernel<<<ROWS, 256>>>(x, ln1_g, ln1_b, xnh, xnl);

    // 2. QKV projections
    dim3 gproj(HID/BN, ROWS/BM);
    tc_gemm<0><<<gproj, 256, GEMM_SMEM>>>(xnh, xnl, wqh, wql, nullptr, q, nullptr, nullptr, HID, HID);
    tc_gemm<0><<<gproj, 256, GEMM_SMEM>>>(xnh, xnl, wkh, wkl, nullptr, k, nullptr, nullptr, HID, HID);
    tc_gemm<0><<<gproj, 256, GEMM_SMEM>>>(xnh, xnl, wvh, wvl, nullptr, v, nullptr, nullptr, HID, HID);

    // 3. causal flash attention -> split att
    dim3 gattn(SEQ/64, BATCH*NHEAD);
    flash_kernel<<<gattn, 256, smem_flash>>>(q, k, v, atth, attl);

    // 4. output projection + residual -> h (fp32)
    tc_gemm<1><<<gproj, 256, GEMM_SMEM>>>(atth, attl, woh, wol, x, h, nullptr, nullptr, HID, HID);

    // 5. LN2 -> split
    ln_kernel<<<ROWS, 256>>>(h, ln2_g, ln2_b, hnh, hnl);

    // 6. FFN up + GELU -> split ff
    dim3 gff1(FFD/BN, ROWS/BM);
    tc_gemm<2><<<gff1, 256, GEMM_SMEM>>>(hnh, hnl, winh, winl, nullptr, nullptr, ffh, ffl, FFD, HID);

    // 7. FFN down + residual -> d_out (fp32)
    dim3 gff2(HID/BN, ROWS/BM);
    tc_gemm<1><<<gff2, 256, GEMM_SMEM>>>(ffh, ffl, wouth, woutl, h, out, nullptr, nullptr, HID, FFD);
}